// round 14
// baseline (speedup 1.0000x reference)
#include <cuda_runtime.h>
#include <cuda_fp16.h>
#include <cstdint>
#include <cstddef>

// Problem constants
#define BB 2
#define TT 2048
#define DD 1024
#define NHEAD 16
#define HDIM 64
#define MROWS (BB * TT)        // 4096
#define QKV_LD (3 * DD)        // 3072
#define NHEADS_TOT (BB * NHEAD)

// Scratch (allocation-free rule: __device__ globals). All operands fp16.
__device__ __half g_xh[(size_t)MROWS * DD];           // x hi
__device__ __half g_xl[(size_t)MROWS * DD];           // x lo (exact split)
__device__ __half g_wah[(size_t)QKV_LD * DD];         // w_attn^T fp16 [3072][1024]
__device__ __half g_wph[(size_t)DD * DD];             // w_proj^T fp16 [1024][1024]
__device__ __half g_ah[(size_t)MROWS * DD];           // attn out fp16
// Head-blocked fp16 for attention: [b*16+n][t][64]
__device__ __half g_qh[(size_t)NHEADS_TOT * TT * HDIM];
__device__ __half g_ql[(size_t)NHEADS_TOT * TT * HDIM];
__device__ __half g_kh[(size_t)NHEADS_TOT * TT * HDIM];
__device__ __half g_vh[(size_t)NHEADS_TOT * TT * HDIM];

// ===========================================================================
// Base-PTX helpers
// ===========================================================================
__device__ __forceinline__ uint32_t smem_u32(const void* p) {
    uint32_t a;
    asm("{ .reg .u64 t; cvta.to.shared.u64 t, %1; cvt.u32.u64 %0, t; }"
        : "=r"(a) : "l"(p));
    return a;
}

#define CP_ASYNC16(saddr, gptr) \
    asm volatile("cp.async.cg.shared.global [%0], [%1], 16;" \
                 :: "r"(saddr), "l"(gptr))
#define CP_COMMIT() asm volatile("cp.async.commit_group;" ::: "memory")
#define CP_WAIT(n)  asm volatile("cp.async.wait_group %0;" :: "n"(n) : "memory")

#define LDSM_X4(r, addr) \
    asm volatile("ldmatrix.sync.aligned.m8n8.x4.shared.b16 {%0,%1,%2,%3}, [%4];" \
                 : "=r"((r)[0]), "=r"((r)[1]), "=r"((r)[2]), "=r"((r)[3]) \
                 : "r"(addr))
#define LDSM_X4_T(r, addr) \
    asm volatile("ldmatrix.sync.aligned.m8n8.x4.trans.shared.b16 {%0,%1,%2,%3}, [%4];" \
                 : "=r"((r)[0]), "=r"((r)[1]), "=r"((r)[2]), "=r"((r)[3]) \
                 : "r"(addr))

#define MMAF16(c, a, b0, b1) \
    asm volatile("mma.sync.aligned.m16n8k16.row.col.f32.f16.f16.f32 " \
                 "{%0,%1,%2,%3},{%4,%5,%6,%7},{%8,%9},{%0,%1,%2,%3};" \
                 : "+f"((c)[0]), "+f"((c)[1]), "+f"((c)[2]), "+f"((c)[3]) \
                 : "r"((a)[0]), "r"((a)[1]), "r"((a)[2]), "r"((a)[3]), \
                   "r"(b0), "r"(b1))

// Split two fp32 into packed fp16 hi + fp16 residual (a -> low half).
__device__ __forceinline__ void split2(float a, float b,
                                       uint32_t& hi, uint32_t& lo) {
    __half ha = __float2half_rn(a), hb = __float2half_rn(b);
    __half la = __float2half_rn(a - __half2float(ha));
    __half lb = __float2half_rn(b - __half2float(hb));
    __half2 H = __halves2half2(ha, hb);
    __half2 L = __halves2half2(la, lb);
    hi = *reinterpret_cast<uint32_t*>(&H);
    lo = *reinterpret_cast<uint32_t*>(&L);
}
__device__ __forceinline__ uint32_t pkh(float a, float b) {
    __half2 H = __halves2half2(__float2half_rn(a), __float2half_rn(b));
    return *reinterpret_cast<uint32_t*>(&H);
}

// ===========================================================================
// Split fp32 -> fp16 hi/lo (elementwise), for x
// ===========================================================================
__global__ __launch_bounds__(256) void split_hilo_kernel(
    const float* __restrict__ in, __half* __restrict__ hi,
    __half* __restrict__ lo, int n4) {
    int i = blockIdx.x * 256 + threadIdx.x;
    if (i >= n4) return;
    float4 v = reinterpret_cast<const float4*>(in)[i];
    uint32_t h0, l0, h1, l1;
    split2(v.x, v.y, h0, l0);
    split2(v.z, v.w, h1, l1);
    *reinterpret_cast<uint2*>(hi + 4 * (size_t)i) = make_uint2(h0, h1);
    *reinterpret_cast<uint2*>(lo + 4 * (size_t)i) = make_uint2(l0, l1);
}

// ===========================================================================
// Transpose: w [K][N] fp32 -> out [N][K] fp16
// ===========================================================================
__global__ __launch_bounds__(256) void transpose_h_kernel(
    const float* __restrict__ w, __half* __restrict__ hi, int K, int N) {
    __shared__ float t[32][33];
    const int tx = threadIdx.x, ty = threadIdx.y;
    const int n_in = blockIdx.x * 32 + tx;
    const int k0   = blockIdx.y * 32;
#pragma unroll
    for (int j = ty; j < 32; j += 8)
        t[j][tx] = w[(size_t)(k0 + j) * N + n_in];
    __syncthreads();
    const int ko = k0 + tx;
    const int n0 = blockIdx.x * 32;
#pragma unroll
    for (int j = ty; j < 32; j += 8)
        hi[(size_t)(n0 + j) * K + ko] = __float2half_rn(t[tx][j]);
}

// ===========================================================================
// Warp-MMA fp16 GEMM: C = A @ fp16(W)^T + bias.
//   np2=1: A = Ah + Al (2 products, exact A).  np2=0: A = Ah (1 product).
// CTA 128x128, 8 warps (warp 64x32), 2-stage cp.async (96KB) -> 2 CTAs/SM.
// mode 0: fp32 C. mode 1: fused QKV epilogue (q/k/v split + head-block).
// ===========================================================================
#define GSTAGE 49152   // Ah 16K | Al 16K | Bh 16K
extern __shared__ char mm_smem[];

__global__ __launch_bounds__(256, 2) void mma_gemm8_kernel(
    const __half* __restrict__ Ahi, const __half* __restrict__ Alo,
    const __half* __restrict__ Bhi,
    const float* __restrict__ bias, float* __restrict__ C,
    float* __restrict__ v_out, int N, int K, int mode, int np2) {
    const int tid  = threadIdx.x;
    const int wid  = tid >> 5;
    const int lane = tid & 31;
    const int m0 = blockIdx.y * 128;
    const int n0 = blockIdx.x * 128;
    const uint32_t sbase = smem_u32(mm_smem);

    float acc[16][4];
#pragma unroll
    for (int i = 0; i < 16; i++)
#pragma unroll
        for (int j = 0; j < 4; j++) acc[i][j] = 0.f;

    auto issue = [&](int kc, int s) {
        const uint32_t buf = sbase + s * GSTAGE;
        const int k0 = kc * 64;
#pragma unroll
        for (int i = 0; i < 4; i++) {
            const int chunk = tid + i * 256;       // 0..1023
            const int r = chunk >> 3;              // row 0..127
            const int c = chunk & 7;               // 16B chunk 0..7
            const uint32_t soff = r * 128 + 16 * (c ^ (r & 7));
            const size_t ga = (size_t)(m0 + r) * K + k0 + c * 8;
            const size_t gb = (size_t)(n0 + r) * K + k0 + c * 8;
            CP_ASYNC16(buf + soff,         Ahi + ga);
            if (np2) CP_ASYNC16(buf + 16384 + soff, Alo + ga);
            CP_ASYNC16(buf + 32768 + soff, Bhi + gb);
        }
    };

    const int mrow0 = (wid >> 2) * 64;
    const int ncol0 = (wid & 3) * 32;
    const int a_r  = lane & 15;
    const int a_kb = lane >> 4;
    const int b_r  = ((lane >> 4) << 3) + (lane & 7);
    const int b_kb = (lane >> 3) & 1;

    auto compute = [&](int s) {
        const uint32_t buf = sbase + s * GSTAGE;
#pragma unroll
        for (int kk = 0; kk < 4; kk++) {
            uint32_t ah[4][4], al[4][4], bh[2][4];
#pragma unroll
            for (int mi = 0; mi < 4; mi++) {
                const int r  = mrow0 + mi * 16 + a_r;
                const int kb = kk * 2 + a_kb;
                const uint32_t addr = buf + r * 128 + 16 * (kb ^ (r & 7));
                LDSM_X4(ah[mi], addr);
                if (np2) LDSM_X4(al[mi], addr + 16384);
            }
#pragma unroll
            for (int nj2 = 0; nj2 < 2; nj2++) {
                const int r  = ncol0 + nj2 * 16 + b_r;
                const int kb = kk * 2 + b_kb;
                const uint32_t addr = buf + 32768 + r * 128 + 16 * (kb ^ (r & 7));
                LDSM_X4(bh[nj2], addr);
            }
            // Product-major: 16 independent MMAs between acc touches
#pragma unroll
            for (int mi = 0; mi < 4; mi++)
#pragma unroll
                for (int nj = 0; nj < 4; nj++) {
                    float* c = acc[mi * 4 + nj];
                    const int g = nj >> 1, sx = (nj & 1) * 2;
                    MMAF16(c, ah[mi], bh[g][sx], bh[g][sx + 1]);
                }
            if (np2) {
#pragma unroll
                for (int mi = 0; mi < 4; mi++)
#pragma unroll
                    for (int nj = 0; nj < 4; nj++) {
                        float* c = acc[mi * 4 + nj];
                        const int g = nj >> 1, sx = (nj & 1) * 2;
                        MMAF16(c, al[mi], bh[g][sx], bh[g][sx + 1]);
                    }
            }
        }
    };

    // ---- 2-stage double-buffered mainloop ----
    const int nch = K >> 6;
    issue(0, 0);
    CP_COMMIT();
    for (int kc = 0; kc < nch; kc++) {
        if (kc + 1 < nch) {
            issue(kc + 1, (kc + 1) & 1);
            CP_COMMIT();
            CP_WAIT(1);
        } else {
            CP_WAIT(0);
        }
        __syncthreads();
        compute(kc & 1);
        __syncthreads();
    }

    // ---- Epilogue ----
    const int rg = lane >> 2, cp2 = (lane & 3) * 2;

    auto emit_qkv = [&](int row, int col, float v0, float v1) {
        const int sector = col >> 10;           // 0=q, 1=k, 2=v
        const int cc = col & 1023;
        const int hn = cc >> 6, hd = cc & 63;
        const int b = row >> 11, t = row & 2047;
        const size_t dst = (((size_t)(b * NHEAD + hn) * TT + t) * HDIM + hd) >> 1;
        if (sector == 0) {
            v0 *= 0.125f; v1 *= 0.125f;
            uint32_t h, lo;
            split2(v0, v1, h, lo);
            reinterpret_cast<uint32_t*>(g_qh)[dst] = h;
            reinterpret_cast<uint32_t*>(g_ql)[dst] = lo;
        } else if (sector == 1) {
            reinterpret_cast<uint32_t*>(g_kh)[dst] = pkh(v0, v1);
            *reinterpret_cast<float2*>(&C[(size_t)row * DD + cc]) =
                make_float2(v0, v1);
        } else {
            reinterpret_cast<uint32_t*>(g_vh)[dst] = pkh(v0, v1);
            *reinterpret_cast<float2*>(&v_out[(size_t)row * DD + cc]) =
                make_float2(v0, v1);
        }
    };

#pragma unroll
    for (int mi = 0; mi < 4; mi++)
#pragma unroll
        for (int nj = 0; nj < 4; nj++) {
            const float* c = acc[mi * 4 + nj];
            const int row = m0 + mrow0 + mi * 16 + rg;
            const int col = n0 + ncol0 + nj * 8 + cp2;
            const float2 b2 = *reinterpret_cast<const float2*>(&bias[col]);
            const float u0 = c[0] + b2.x, u1 = c[1] + b2.y;
            const float w0 = c[2] + b2.x, w1 = c[3] + b2.y;
            if (mode == 0) {
                *reinterpret_cast<float2*>(&C[(size_t)row * N + col]) =
                    make_float2(u0, u1);
                *reinterpret_cast<float2*>(&C[(size_t)(row + 8) * N + col]) =
                    make_float2(w0, w1);
            } else {
                emit_qkv(row, col, u0, u1);
                emit_qkv(row + 8, col, w0, w1);
            }
        }
}

// ===========================================================================
// Tensor-core flash attention (fp16, causal).
// S = QK^T: 2 products ((qh+ql)·kh) — q exact, k quantized.
// O += PV: 1 product (fp16(P)·Vh).
// smem: Qh|Ql (16KB) + 2 x (Kh|Vh) (2x16KB) = 48KB.
// ===========================================================================
extern __shared__ char fa3_smem[];

__global__ __launch_bounds__(128) void flash6_kernel() {
    const int qt = (TT / 64 - 1) - blockIdx.x;
    const int hidx = blockIdx.y;                 // b*16+n
    const int tid = threadIdx.x;
    const int w = tid >> 5;
    const int l = tid & 31;

    const uint32_t S = smem_u32(fa3_smem);
    const uint32_t sQh = S, sQl = S + 8192;

    const size_t hb = (size_t)hidx * TT * HDIM;
    const __half* qh = g_qh + hb + (size_t)qt * 64 * HDIM;
    const __half* ql = g_ql + hb + (size_t)qt * 64 * HDIM;
    const __half* kh = g_kh + hb;
    const __half* vh = g_vh + hb;

    auto issueQ = [&]() {
#pragma unroll
        for (int i = 0; i < 4; i++) {
            const int chunk = tid + i * 128;
            const int r = chunk >> 3, c = chunk & 7;
            const uint32_t soff = r * 128 + 16 * (c ^ (r & 7));
            CP_ASYNC16(sQh + soff, qh + r * HDIM + c * 8);
            CP_ASYNC16(sQl + soff, ql + r * HDIM + c * 8);
        }
    };
    auto issueKV = [&](int jt, int sel) {
        const uint32_t base = S + 16384 + sel * 16384;
        const size_t toff = (size_t)jt * 64 * HDIM;
#pragma unroll
        for (int i = 0; i < 4; i++) {
            const int chunk = tid + i * 128;
            const int r = chunk >> 3, c = chunk & 7;
            const uint32_t soff = r * 128 + 16 * (c ^ (r & 7));
            const size_t g = toff + r * HDIM + c * 8;
            CP_ASYNC16(base + soff,        kh + g);
            CP_ASYNC16(base + 8192 + soff, vh + g);
        }
    };

    issueQ();
    issueKV(0, 0);
    CP_COMMIT();

    float o[8][4];
#pragma unroll
    for (int i = 0; i < 8; i++)
#pragma unroll
        for (int j = 0; j < 4; j++) o[i][j] = 0.f;
    float m0 = -1e30f, m1 = -1e30f, l0 = 0.f, l1 = 0.f;

    const int a_r  = l & 15;
    const int a_kb = l >> 4;
    const int b_r  = ((l >> 4) << 3) + (l & 7);
    const int b_kb = (l >> 3) & 1;

    for (int jt = 0; jt <= qt; jt++) {
        if (jt < qt) {
            issueKV(jt + 1, (jt + 1) & 1);
            CP_COMMIT();
            CP_WAIT(1);
        } else {
            CP_WAIT(0);
        }
        __syncthreads();
        const uint32_t kvb = S + 16384 + (jt & 1) * 16384;

        float s[8][4];
#pragma unroll
        for (int i = 0; i < 8; i++)
#pragma unroll
            for (int j = 0; j < 4; j++) s[i][j] = 0.f;

#pragma unroll
        for (int kk = 0; kk < 4; kk++) {
            uint32_t qh4[4], ql4[4], kh4[4][4];
            {
                const int r = w * 16 + a_r;
                const int kb = kk * 2 + a_kb;
                const uint32_t addr = sQh + r * 128 + 16 * (kb ^ (r & 7));
                LDSM_X4(qh4, addr);
                LDSM_X4(ql4, addr + 8192);
            }
#pragma unroll
            for (int g = 0; g < 4; g++) {
                const int r = g * 16 + b_r;
                const int kb = kk * 2 + b_kb;
                const uint32_t addr = kvb + r * 128 + 16 * (kb ^ (r & 7));
                LDSM_X4(kh4[g], addr);
            }
#pragma unroll
            for (int p = 0; p < 2; p++)
#pragma unroll
                for (int nj = 0; nj < 8; nj++) {
                    const int g = nj >> 1, sx = (nj & 1) * 2;
                    const uint32_t* aa = (p == 1) ? ql4 : qh4;
                    MMAF16(s[nj], aa, kh4[g][sx], kh4[g][sx + 1]);
                }
        }

        if (jt == qt) {
            const int row0 = w * 16 + (l >> 2);
#pragma unroll
            for (int nj = 0; nj < 8; nj++) {
                const int col = nj * 8 + 2 * (l & 3);
                if (col > row0)          s[nj][0] = -1e30f;
                if (col + 1 > row0)      s[nj][1] = -1e30f;
                if (col > row0 + 8)      s[nj][2] = -1e30f;
                if (col + 1 > row0 + 8)  s[nj][3] = -1e30f;
            }
        }

        {
            float mx0 = s[0][0], mx1 = s[0][2];
#pragma unroll
            for (int nj = 0; nj < 8; nj++) {
                mx0 = fmaxf(mx0, fmaxf(s[nj][0], s[nj][1]));
                mx1 = fmaxf(mx1, fmaxf(s[nj][2], s[nj][3]));
            }
            mx0 = fmaxf(mx0, __shfl_xor_sync(0xffffffffu, mx0, 1));
            mx0 = fmaxf(mx0, __shfl_xor_sync(0xffffffffu, mx0, 2));
            mx1 = fmaxf(mx1, __shfl_xor_sync(0xffffffffu, mx1, 1));
            mx1 = fmaxf(mx1, __shfl_xor_sync(0xffffffffu, mx1, 2));
            const float mn0 = fmaxf(m0, mx0);
            const float mn1 = fmaxf(m1, mx1);
            const float c0 = __expf(m0 - mn0);
            const float c1 = __expf(m1 - mn1);
            float rs0 = 0.f, rs1 = 0.f;
#pragma unroll
            for (int nj = 0; nj < 8; nj++) {
                s[nj][0] = __expf(s[nj][0] - mn0);
                s[nj][1] = __expf(s[nj][1] - mn0);
                s[nj][2] = __expf(s[nj][2] - mn1);
                s[nj][3] = __expf(s[nj][3] - mn1);
                rs0 += s[nj][0] + s[nj][1];
                rs1 += s[nj][2] + s[nj][3];
            }
            rs0 += __shfl_xor_sync(0xffffffffu, rs0, 1);
            rs0 += __shfl_xor_sync(0xffffffffu, rs0, 2);
            rs1 += __shfl_xor_sync(0xffffffffu, rs1, 1);
            rs1 += __shfl_xor_sync(0xffffffffu, rs1, 2);
            l0 = l0 * c0 + rs0; m0 = mn0;
            l1 = l1 * c1 + rs1; m1 = mn1;
#pragma unroll
            for (int nh = 0; nh < 8; nh++) {
                o[nh][0] *= c0; o[nh][1] *= c0;
                o[nh][2] *= c1; o[nh][3] *= c1;
            }
        }

        // ---- O += fp16(P) @ Vh (single product) ----
        const uint32_t vb = kvb + 8192;
#pragma unroll
        for (int kk = 0; kk < 4; kk++) {
            uint32_t phi[4];
            {
                const float* t0 = s[2 * kk];
                const float* t1 = s[2 * kk + 1];
                phi[0] = pkh(t0[0], t0[1]);
                phi[1] = pkh(t0[2], t0[3]);
                phi[2] = pkh(t1[0], t1[1]);
                phi[3] = pkh(t1[2], t1[3]);
            }
            uint32_t vh4[4][4];
#pragma unroll
            for (int g = 0; g < 4; g++) {
                const int row = kk * 16 + (l & 15);
                const int ch  = g * 2 + (l >> 4);
                const uint32_t addr = vb + row * 128 + 16 * (ch ^ (row & 7));
                LDSM_X4_T(vh4[g], addr);
            }
#pragma unroll
            for (int nh = 0; nh < 8; nh++) {
                const int g = nh >> 1, sx = (nh & 1) * 2;
                MMAF16(o[nh], phi, vh4[g][sx], vh4[g][sx + 1]);
            }
        }
        __syncthreads();
    }

    // ---- Epilogue: normalize, store fp16 attn-out ----
    const float inv0 = 1.0f / l0;
    const float inv1 = 1.0f / l1;
    const int b = hidx >> 4, n = hidx & 15;
    const int row0 = qt * 64 + w * 16 + (l >> 2);
#pragma unroll
    for (int nh = 0; nh < 8; nh++) {
        const int col = n * HDIM + nh * 8 + 2 * (l & 3);
        const size_t d0 = ((size_t)(b * TT + row0) * DD + col) >> 1;
        const size_t d1 = ((size_t)(b * TT + row0 + 8) * DD + col) >> 1;
        reinterpret_cast<uint32_t*>(g_ah)[d0] =
            pkh(o[nh][0] * inv0, o[nh][1] * inv0);
        reinterpret_cast<uint32_t*>(g_ah)[d1] =
            pkh(o[nh][2] * inv1, o[nh][3] * inv1);
    }
}

// ---------------------------------------------------------------------------
// Launch
// ---------------------------------------------------------------------------
extern "C" void kernel_launch(void* const* d_in, const int* in_sizes, int n_in,
                              void* d_out, int out_size) {
    (void)in_sizes; (void)n_in; (void)out_size;
    const float* x      = (const float*)d_in[0];
    const float* w_attn = (const float*)d_in[1];
    const float* b_attn = (const float*)d_in[2];
    const float* w_proj = (const float*)d_in[3];
    const float* b_proj = (const float*)d_in[4];

    float* out   = (float*)d_out;
    float* k_out = out + (size_t)MROWS * DD;
    float* v_out = k_out + (size_t)MROWS * DD;

    __half *xh, *xl, *wah, *wph, *ah;
    cudaGetSymbolAddress((void**)&xh, g_xh);
    cudaGetSymbolAddress((void**)&xl, g_xl);
    cudaGetSymbolAddress((void**)&wah, g_wah);
    cudaGetSymbolAddress((void**)&wph, g_wph);
    cudaGetSymbolAddress((void**)&ah, g_ah);

    const int MM_SMEM = 2 * GSTAGE;             // 98304 -> 2 CTAs/SM
    const int FA_SMEM = 16384 + 2 * 16384;      // 49152
    cudaFuncSetAttribute(mma_gemm8_kernel,
                         cudaFuncAttributeMaxDynamicSharedMemorySize, MM_SMEM);
    cudaFuncSetAttribute(flash6_kernel,
                         cudaFuncAttributeMaxDynamicSharedMemorySize, FA_SMEM);

    // Conversions
    split_hilo_kernel<<<(MROWS * DD / 4 + 255) / 256, 256>>>(x, xh, xl, MROWS * DD / 4);
    transpose_h_kernel<<<dim3(QKV_LD / 32, DD / 32), dim3(32, 8)>>>(
        w_attn, wah, DD, QKV_LD);
    transpose_h_kernel<<<dim3(DD / 32, DD / 32), dim3(32, 8)>>>(
        w_proj, wph, DD, DD);

    // 1) QKV projection (2-product, exact x) with fused q/k/v epilogue
    mma_gemm8_kernel<<<dim3(QKV_LD / 128, MROWS / 128), 256, MM_SMEM>>>(
        xh, xl, wah, b_attn, k_out, v_out, QKV_LD, DD, 1, 1);

    // 2) Tensor-core flash attention (S 2-product, PV 1-product)
    flash6_kernel<<<dim3(TT / 64, NHEADS_TOT), 128, FA_SMEM>>>();

    // 3) Output projection (single product — attn-out already fp16)
    mma_gemm8_kernel<<<dim3(DD / 128, MROWS / 128), 256, MM_SMEM>>>(
        ah, ah, wph, b_proj, out, nullptr, DD, DD, 0, 0);
}

// round 15
// speedup vs baseline: 1.0042x; 1.0042x over previous
#include <cuda_runtime.h>
#include <cuda_fp16.h>
#include <cstdint>
#include <cstddef>

// Problem constants
#define BB 2
#define TT 2048
#define DD 1024
#define NHEAD 16
#define HDIM 64
#define MROWS (BB * TT)        // 4096
#define QKV_LD (3 * DD)        // 3072
#define NHEADS_TOT (BB * NHEAD)

// Scratch (allocation-free rule: __device__ globals). All operands fp16.
__device__ __half g_xh[(size_t)MROWS * DD];           // x hi
__device__ __half g_xl[(size_t)MROWS * DD];           // x lo (exact split)
__device__ __half g_wah[(size_t)QKV_LD * DD];         // w_attn^T fp16 [3072][1024]
__device__ __half g_wph[(size_t)DD * DD];             // w_proj^T fp16 [1024][1024]
__device__ __half g_ah[(size_t)MROWS * DD];           // attn out fp16
// Head-blocked fp16 for attention: [b*16+n][t][64]
__device__ __half g_qh[(size_t)NHEADS_TOT * TT * HDIM];
__device__ __half g_ql[(size_t)NHEADS_TOT * TT * HDIM];
__device__ __half g_kh[(size_t)NHEADS_TOT * TT * HDIM];
__device__ __half g_vh[(size_t)NHEADS_TOT * TT * HDIM];

// ===========================================================================
// Base-PTX helpers
// ===========================================================================
__device__ __forceinline__ uint32_t smem_u32(const void* p) {
    uint32_t a;
    asm("{ .reg .u64 t; cvta.to.shared.u64 t, %1; cvt.u32.u64 %0, t; }"
        : "=r"(a) : "l"(p));
    return a;
}

#define CP_ASYNC16(saddr, gptr) \
    asm volatile("cp.async.cg.shared.global [%0], [%1], 16;" \
                 :: "r"(saddr), "l"(gptr))
#define CP_COMMIT() asm volatile("cp.async.commit_group;" ::: "memory")
#define CP_WAIT(n)  asm volatile("cp.async.wait_group %0;" :: "n"(n) : "memory")

#define LDSM_X4(r, addr) \
    asm volatile("ldmatrix.sync.aligned.m8n8.x4.shared.b16 {%0,%1,%2,%3}, [%4];" \
                 : "=r"((r)[0]), "=r"((r)[1]), "=r"((r)[2]), "=r"((r)[3]) \
                 : "r"(addr))
#define LDSM_X4_T(r, addr) \
    asm volatile("ldmatrix.sync.aligned.m8n8.x4.trans.shared.b16 {%0,%1,%2,%3}, [%4];" \
                 : "=r"((r)[0]), "=r"((r)[1]), "=r"((r)[2]), "=r"((r)[3]) \
                 : "r"(addr))

#define MMAF16(c, a, b0, b1) \
    asm volatile("mma.sync.aligned.m16n8k16.row.col.f32.f16.f16.f32 " \
                 "{%0,%1,%2,%3},{%4,%5,%6,%7},{%8,%9},{%0,%1,%2,%3};" \
                 : "+f"((c)[0]), "+f"((c)[1]), "+f"((c)[2]), "+f"((c)[3]) \
                 : "r"((a)[0]), "r"((a)[1]), "r"((a)[2]), "r"((a)[3]), \
                   "r"(b0), "r"(b1))

// Split two fp32 into packed fp16 hi + fp16 residual (a -> low half).
__device__ __forceinline__ void split2(float a, float b,
                                       uint32_t& hi, uint32_t& lo) {
    __half ha = __float2half_rn(a), hb = __float2half_rn(b);
    __half la = __float2half_rn(a - __half2float(ha));
    __half lb = __float2half_rn(b - __half2float(hb));
    __half2 H = __halves2half2(ha, hb);
    __half2 L = __halves2half2(la, lb);
    hi = *reinterpret_cast<uint32_t*>(&H);
    lo = *reinterpret_cast<uint32_t*>(&L);
}
__device__ __forceinline__ uint32_t pkh(float a, float b) {
    __half2 H = __halves2half2(__float2half_rn(a), __float2half_rn(b));
    return *reinterpret_cast<uint32_t*>(&H);
}

// ===========================================================================
// Split fp32 -> fp16 hi/lo (elementwise), for x
// ===========================================================================
__global__ __launch_bounds__(256) void split_hilo_kernel(
    const float* __restrict__ in, __half* __restrict__ hi,
    __half* __restrict__ lo, int n4) {
    int i = blockIdx.x * 256 + threadIdx.x;
    if (i >= n4) return;
    float4 v = reinterpret_cast<const float4*>(in)[i];
    uint32_t h0, l0, h1, l1;
    split2(v.x, v.y, h0, l0);
    split2(v.z, v.w, h1, l1);
    *reinterpret_cast<uint2*>(hi + 4 * (size_t)i) = make_uint2(h0, h1);
    *reinterpret_cast<uint2*>(lo + 4 * (size_t)i) = make_uint2(l0, l1);
}

// ===========================================================================
// Transpose: w [K][N] fp32 -> out [N][K] fp16
// ===========================================================================
__global__ __launch_bounds__(256) void transpose_h_kernel(
    const float* __restrict__ w, __half* __restrict__ hi, int K, int N) {
    __shared__ float t[32][33];
    const int tx = threadIdx.x, ty = threadIdx.y;
    const int n_in = blockIdx.x * 32 + tx;
    const int k0   = blockIdx.y * 32;
#pragma unroll
    for (int j = ty; j < 32; j += 8)
        t[j][tx] = w[(size_t)(k0 + j) * N + n_in];
    __syncthreads();
    const int ko = k0 + tx;
    const int n0 = blockIdx.x * 32;
#pragma unroll
    for (int j = ty; j < 32; j += 8)
        hi[(size_t)(n0 + j) * K + ko] = __float2half_rn(t[tx][j]);
}

// ===========================================================================
// Warp-MMA fp16 GEMM: C = A @ fp16(W)^T + bias.
//   np2=1: A = Ah + Al (2 products, exact A).  np2=0: A = Ah (1 product).
// CTA 128x128, 8 warps (warp 64x32), 2-stage cp.async (96KB) -> 2 CTAs/SM.
// mode 0: fp32 C. mode 1: fused QKV epilogue (q/k/v split + head-block).
// ===========================================================================
#define GSTAGE 49152   // Ah 16K | Al 16K | Bh 16K
extern __shared__ char mm_smem[];

__global__ __launch_bounds__(256, 2) void mma_gemm8_kernel(
    const __half* __restrict__ Ahi, const __half* __restrict__ Alo,
    const __half* __restrict__ Bhi,
    const float* __restrict__ bias, float* __restrict__ C,
    float* __restrict__ v_out, int N, int K, int mode, int np2) {
    const int tid  = threadIdx.x;
    const int wid  = tid >> 5;
    const int lane = tid & 31;
    const int m0 = blockIdx.y * 128;
    const int n0 = blockIdx.x * 128;
    const uint32_t sbase = smem_u32(mm_smem);

    float acc[16][4];
#pragma unroll
    for (int i = 0; i < 16; i++)
#pragma unroll
        for (int j = 0; j < 4; j++) acc[i][j] = 0.f;

    auto issue = [&](int kc, int s) {
        const uint32_t buf = sbase + s * GSTAGE;
        const int k0 = kc * 64;
#pragma unroll
        for (int i = 0; i < 4; i++) {
            const int chunk = tid + i * 256;       // 0..1023
            const int r = chunk >> 3;              // row 0..127
            const int c = chunk & 7;               // 16B chunk 0..7
            const uint32_t soff = r * 128 + 16 * (c ^ (r & 7));
            const size_t ga = (size_t)(m0 + r) * K + k0 + c * 8;
            const size_t gb = (size_t)(n0 + r) * K + k0 + c * 8;
            CP_ASYNC16(buf + soff,         Ahi + ga);
            if (np2) CP_ASYNC16(buf + 16384 + soff, Alo + ga);
            CP_ASYNC16(buf + 32768 + soff, Bhi + gb);
        }
    };

    const int mrow0 = (wid >> 2) * 64;
    const int ncol0 = (wid & 3) * 32;
    const int a_r  = lane & 15;
    const int a_kb = lane >> 4;
    const int b_r  = ((lane >> 4) << 3) + (lane & 7);
    const int b_kb = (lane >> 3) & 1;

    auto compute = [&](int s) {
        const uint32_t buf = sbase + s * GSTAGE;
#pragma unroll
        for (int kk = 0; kk < 4; kk++) {
            uint32_t ah[4][4], al[4][4], bh[2][4];
#pragma unroll
            for (int mi = 0; mi < 4; mi++) {
                const int r  = mrow0 + mi * 16 + a_r;
                const int kb = kk * 2 + a_kb;
                const uint32_t addr = buf + r * 128 + 16 * (kb ^ (r & 7));
                LDSM_X4(ah[mi], addr);
                if (np2) LDSM_X4(al[mi], addr + 16384);
            }
#pragma unroll
            for (int nj2 = 0; nj2 < 2; nj2++) {
                const int r  = ncol0 + nj2 * 16 + b_r;
                const int kb = kk * 2 + b_kb;
                const uint32_t addr = buf + 32768 + r * 128 + 16 * (kb ^ (r & 7));
                LDSM_X4(bh[nj2], addr);
            }
            // Product-major: 16 independent MMAs between acc touches
#pragma unroll
            for (int mi = 0; mi < 4; mi++)
#pragma unroll
                for (int nj = 0; nj < 4; nj++) {
                    float* c = acc[mi * 4 + nj];
                    const int g = nj >> 1, sx = (nj & 1) * 2;
                    MMAF16(c, ah[mi], bh[g][sx], bh[g][sx + 1]);
                }
            if (np2) {
#pragma unroll
                for (int mi = 0; mi < 4; mi++)
#pragma unroll
                    for (int nj = 0; nj < 4; nj++) {
                        float* c = acc[mi * 4 + nj];
                        const int g = nj >> 1, sx = (nj & 1) * 2;
                        MMAF16(c, al[mi], bh[g][sx], bh[g][sx + 1]);
                    }
            }
        }
    };

    // ---- 2-stage double-buffered mainloop ----
    const int nch = K >> 6;
    issue(0, 0);
    CP_COMMIT();
    for (int kc = 0; kc < nch; kc++) {
        if (kc + 1 < nch) {
            issue(kc + 1, (kc + 1) & 1);
            CP_COMMIT();
            CP_WAIT(1);
        } else {
            CP_WAIT(0);
        }
        __syncthreads();
        compute(kc & 1);
        __syncthreads();
    }

    // ---- Epilogue ----
    const int rg = lane >> 2, cp2 = (lane & 3) * 2;

    auto emit_qkv = [&](int row, int col, float v0, float v1) {
        const int sector = col >> 10;           // 0=q, 1=k, 2=v
        const int cc = col & 1023;
        const int hn = cc >> 6, hd = cc & 63;
        const int b = row >> 11, t = row & 2047;
        const size_t dst = (((size_t)(b * NHEAD + hn) * TT + t) * HDIM + hd) >> 1;
        if (sector == 0) {
            v0 *= 0.125f; v1 *= 0.125f;
            uint32_t h, lo;
            split2(v0, v1, h, lo);
            reinterpret_cast<uint32_t*>(g_qh)[dst] = h;
            reinterpret_cast<uint32_t*>(g_ql)[dst] = lo;
        } else if (sector == 1) {
            reinterpret_cast<uint32_t*>(g_kh)[dst] = pkh(v0, v1);
            *reinterpret_cast<float2*>(&C[(size_t)row * DD + cc]) =
                make_float2(v0, v1);
        } else {
            reinterpret_cast<uint32_t*>(g_vh)[dst] = pkh(v0, v1);
            *reinterpret_cast<float2*>(&v_out[(size_t)row * DD + cc]) =
                make_float2(v0, v1);
        }
    };

#pragma unroll
    for (int mi = 0; mi < 4; mi++)
#pragma unroll
        for (int nj = 0; nj < 4; nj++) {
            const float* c = acc[mi * 4 + nj];
            const int row = m0 + mrow0 + mi * 16 + rg;
            const int col = n0 + ncol0 + nj * 8 + cp2;
            const float2 b2 = *reinterpret_cast<const float2*>(&bias[col]);
            const float u0 = c[0] + b2.x, u1 = c[1] + b2.y;
            const float w0 = c[2] + b2.x, w1 = c[3] + b2.y;
            if (mode == 0) {
                *reinterpret_cast<float2*>(&C[(size_t)row * N + col]) =
                    make_float2(u0, u1);
                *reinterpret_cast<float2*>(&C[(size_t)(row + 8) * N + col]) =
                    make_float2(w0, w1);
            } else {
                emit_qkv(row, col, u0, u1);
                emit_qkv(row + 8, col, w0, w1);
            }
        }
}

// ===========================================================================
// Tensor-core flash attention (fp16, causal).
// S = QK^T: 2 products ((qh+ql)·kh) — q exact, k quantized.
// O += PV: 1 product (fp16(P)·Vh).
// smem: Qh|Ql (16KB) + 2 x (Kh|Vh) (2x16KB) = 48KB.
// ===========================================================================
extern __shared__ char fa3_smem[];

__global__ __launch_bounds__(128) void flash6_kernel() {
    const int qt = (TT / 64 - 1) - blockIdx.x;
    const int hidx = blockIdx.y;                 // b*16+n
    const int tid = threadIdx.x;
    const int w = tid >> 5;
    const int l = tid & 31;

    const uint32_t S = smem_u32(fa3_smem);
    const uint32_t sQh = S, sQl = S + 8192;

    const size_t hb = (size_t)hidx * TT * HDIM;
    const __half* qh = g_qh + hb + (size_t)qt * 64 * HDIM;
    const __half* ql = g_ql + hb + (size_t)qt * 64 * HDIM;
    const __half* kh = g_kh + hb;
    const __half* vh = g_vh + hb;

    auto issueQ = [&]() {
#pragma unroll
        for (int i = 0; i < 4; i++) {
            const int chunk = tid + i * 128;
            const int r = chunk >> 3, c = chunk & 7;
            const uint32_t soff = r * 128 + 16 * (c ^ (r & 7));
            CP_ASYNC16(sQh + soff, qh + r * HDIM + c * 8);
            CP_ASYNC16(sQl + soff, ql + r * HDIM + c * 8);
        }
    };
    auto issueKV = [&](int jt, int sel) {
        const uint32_t base = S + 16384 + sel * 16384;
        const size_t toff = (size_t)jt * 64 * HDIM;
#pragma unroll
        for (int i = 0; i < 4; i++) {
            const int chunk = tid + i * 128;
            const int r = chunk >> 3, c = chunk & 7;
            const uint32_t soff = r * 128 + 16 * (c ^ (r & 7));
            const size_t g = toff + r * HDIM + c * 8;
            CP_ASYNC16(base + soff,        kh + g);
            CP_ASYNC16(base + 8192 + soff, vh + g);
        }
    };

    issueQ();
    issueKV(0, 0);
    CP_COMMIT();

    float o[8][4];
#pragma unroll
    for (int i = 0; i < 8; i++)
#pragma unroll
        for (int j = 0; j < 4; j++) o[i][j] = 0.f;
    float m0 = -1e30f, m1 = -1e30f, l0 = 0.f, l1 = 0.f;

    const int a_r  = l & 15;
    const int a_kb = l >> 4;
    const int b_r  = ((l >> 4) << 3) + (l & 7);
    const int b_kb = (l >> 3) & 1;

    for (int jt = 0; jt <= qt; jt++) {
        if (jt < qt) {
            issueKV(jt + 1, (jt + 1) & 1);
            CP_COMMIT();
            CP_WAIT(1);
        } else {
            CP_WAIT(0);
        }
        __syncthreads();
        const uint32_t kvb = S + 16384 + (jt & 1) * 16384;

        float s[8][4];
#pragma unroll
        for (int i = 0; i < 8; i++)
#pragma unroll
            for (int j = 0; j < 4; j++) s[i][j] = 0.f;

#pragma unroll
        for (int kk = 0; kk < 4; kk++) {
            uint32_t qh4[4], ql4[4], kh4[4][4];
            {
                const int r = w * 16 + a_r;
                const int kb = kk * 2 + a_kb;
                const uint32_t addr = sQh + r * 128 + 16 * (kb ^ (r & 7));
                LDSM_X4(qh4, addr);
                LDSM_X4(ql4, addr + 8192);
            }
#pragma unroll
            for (int g = 0; g < 4; g++) {
                const int r = g * 16 + b_r;
                const int kb = kk * 2 + b_kb;
                const uint32_t addr = kvb + r * 128 + 16 * (kb ^ (r & 7));
                LDSM_X4(kh4[g], addr);
            }
#pragma unroll
            for (int p = 0; p < 2; p++)
#pragma unroll
                for (int nj = 0; nj < 8; nj++) {
                    const int g = nj >> 1, sx = (nj & 1) * 2;
                    const uint32_t* aa = (p == 1) ? ql4 : qh4;
                    MMAF16(s[nj], aa, kh4[g][sx], kh4[g][sx + 1]);
                }
        }

        if (jt == qt) {
            const int row0 = w * 16 + (l >> 2);
#pragma unroll
            for (int nj = 0; nj < 8; nj++) {
                const int col = nj * 8 + 2 * (l & 3);
                if (col > row0)          s[nj][0] = -1e30f;
                if (col + 1 > row0)      s[nj][1] = -1e30f;
                if (col > row0 + 8)      s[nj][2] = -1e30f;
                if (col + 1 > row0 + 8)  s[nj][3] = -1e30f;
            }
        }

        {
            float mx0 = s[0][0], mx1 = s[0][2];
#pragma unroll
            for (int nj = 0; nj < 8; nj++) {
                mx0 = fmaxf(mx0, fmaxf(s[nj][0], s[nj][1]));
                mx1 = fmaxf(mx1, fmaxf(s[nj][2], s[nj][3]));
            }
            mx0 = fmaxf(mx0, __shfl_xor_sync(0xffffffffu, mx0, 1));
            mx0 = fmaxf(mx0, __shfl_xor_sync(0xffffffffu, mx0, 2));
            mx1 = fmaxf(mx1, __shfl_xor_sync(0xffffffffu, mx1, 1));
            mx1 = fmaxf(mx1, __shfl_xor_sync(0xffffffffu, mx1, 2));
            const float mn0 = fmaxf(m0, mx0);
            const float mn1 = fmaxf(m1, mx1);
            const float c0 = __expf(m0 - mn0);
            const float c1 = __expf(m1 - mn1);
            float rs0 = 0.f, rs1 = 0.f;
#pragma unroll
            for (int nj = 0; nj < 8; nj++) {
                s[nj][0] = __expf(s[nj][0] - mn0);
                s[nj][1] = __expf(s[nj][1] - mn0);
                s[nj][2] = __expf(s[nj][2] - mn1);
                s[nj][3] = __expf(s[nj][3] - mn1);
                rs0 += s[nj][0] + s[nj][1];
                rs1 += s[nj][2] + s[nj][3];
            }
            rs0 += __shfl_xor_sync(0xffffffffu, rs0, 1);
            rs0 += __shfl_xor_sync(0xffffffffu, rs0, 2);
            rs1 += __shfl_xor_sync(0xffffffffu, rs1, 1);
            rs1 += __shfl_xor_sync(0xffffffffu, rs1, 2);
            l0 = l0 * c0 + rs0; m0 = mn0;
            l1 = l1 * c1 + rs1; m1 = mn1;
#pragma unroll
            for (int nh = 0; nh < 8; nh++) {
                o[nh][0] *= c0; o[nh][1] *= c0;
                o[nh][2] *= c1; o[nh][3] *= c1;
            }
        }

        // ---- O += fp16(P) @ Vh (single product) ----
        const uint32_t vb = kvb + 8192;
#pragma unroll
        for (int kk = 0; kk < 4; kk++) {
            uint32_t phi[4];
            {
                const float* t0 = s[2 * kk];
                const float* t1 = s[2 * kk + 1];
                phi[0] = pkh(t0[0], t0[1]);
                phi[1] = pkh(t0[2], t0[3]);
                phi[2] = pkh(t1[0], t1[1]);
                phi[3] = pkh(t1[2], t1[3]);
            }
            uint32_t vh4[4][4];
#pragma unroll
            for (int g = 0; g < 4; g++) {
                const int row = kk * 16 + (l & 15);
                const int ch  = g * 2 + (l >> 4);
                const uint32_t addr = vb + row * 128 + 16 * (ch ^ (row & 7));
                LDSM_X4_T(vh4[g], addr);
            }
#pragma unroll
            for (int nh = 0; nh < 8; nh++) {
                const int g = nh >> 1, sx = (nh & 1) * 2;
                MMAF16(o[nh], phi, vh4[g][sx], vh4[g][sx + 1]);
            }
        }
        __syncthreads();
    }

    // ---- Epilogue: normalize, store fp16 attn-out ----
    const float inv0 = 1.0f / l0;
    const float inv1 = 1.0f / l1;
    const int b = hidx >> 4, n = hidx & 15;
    const int row0 = qt * 64 + w * 16 + (l >> 2);
#pragma unroll
    for (int nh = 0; nh < 8; nh++) {
        const int col = n * HDIM + nh * 8 + 2 * (l & 3);
        const size_t d0 = ((size_t)(b * TT + row0) * DD + col) >> 1;
        const size_t d1 = ((size_t)(b * TT + row0 + 8) * DD + col) >> 1;
        reinterpret_cast<uint32_t*>(g_ah)[d0] =
            pkh(o[nh][0] * inv0, o[nh][1] * inv0);
        reinterpret_cast<uint32_t*>(g_ah)[d1] =
            pkh(o[nh][2] * inv1, o[nh][3] * inv1);
    }
}

// ---------------------------------------------------------------------------
// Launch
// ---------------------------------------------------------------------------
extern "C" void kernel_launch(void* const* d_in, const int* in_sizes, int n_in,
                              void* d_out, int out_size) {
    (void)in_sizes; (void)n_in; (void)out_size;
    const float* x      = (const float*)d_in[0];
    const float* w_attn = (const float*)d_in[1];
    const float* b_attn = (const float*)d_in[2];
    const float* w_proj = (const float*)d_in[3];
    const float* b_proj = (const float*)d_in[4];

    float* out   = (float*)d_out;
    float* k_out = out + (size_t)MROWS * DD;
    float* v_out = k_out + (size_t)MROWS * DD;

    __half *xh, *xl, *wah, *wph, *ah;
    cudaGetSymbolAddress((void**)&xh, g_xh);
    cudaGetSymbolAddress((void**)&xl, g_xl);
    cudaGetSymbolAddress((void**)&wah, g_wah);
    cudaGetSymbolAddress((void**)&wph, g_wph);
    cudaGetSymbolAddress((void**)&ah, g_ah);

    const int MM_SMEM = 2 * GSTAGE;             // 98304 -> 2 CTAs/SM
    const int FA_SMEM = 16384 + 2 * 16384;      // 49152
    cudaFuncSetAttribute(mma_gemm8_kernel,
                         cudaFuncAttributeMaxDynamicSharedMemorySize, MM_SMEM);
    cudaFuncSetAttribute(flash6_kernel,
                         cudaFuncAttributeMaxDynamicSharedMemorySize, FA_SMEM);

    // Conversions
    split_hilo_kernel<<<(MROWS * DD / 4 + 255) / 256, 256>>>(x, xh, xl, MROWS * DD / 4);
    transpose_h_kernel<<<dim3(QKV_LD / 32, DD / 32), dim3(32, 8)>>>(
        w_attn, wah, DD, QKV_LD);
    transpose_h_kernel<<<dim3(DD / 32, DD / 32), dim3(32, 8)>>>(
        w_proj, wph, DD, DD);

    // 1) QKV projection (2-product, exact x) with fused q/k/v epilogue
    mma_gemm8_kernel<<<dim3(QKV_LD / 128, MROWS / 128), 256, MM_SMEM>>>(
        xh, xl, wah, b_attn, k_out, v_out, QKV_LD, DD, 1, 1);

    // 2) Tensor-core flash attention (S 2-product, PV 1-product)
    flash6_kernel<<<dim3(TT / 64, NHEADS_TOT), 128, FA_SMEM>>>();

    // 3) Output projection (single product — attn-out already fp16)
    mma_gemm8_kernel<<<dim3(DD / 128, MROWS / 128), 256, MM_SMEM>>>(
        ah, ah, wph, b_proj, out, nullptr, DD, DD, 0, 0);
}

// round 16
// speedup vs baseline: 1.4446x; 1.4386x over previous
#include <cuda_runtime.h>
#include <cuda_fp16.h>
#include <cstdint>
#include <cstddef>

// Problem constants
#define BB 2
#define TT 2048
#define DD 1024
#define NHEAD 16
#define HDIM 64
#define MROWS (BB * TT)        // 4096
#define QKV_LD (3 * DD)        // 3072
#define NHEADS_TOT (BB * NHEAD)

// Scratch (allocation-free rule: __device__ globals). All operands fp16.
__device__ __half g_xh[(size_t)MROWS * DD];           // x hi
__device__ __half g_xl[(size_t)MROWS * DD];           // x lo (exact split)
__device__ __half g_wah[(size_t)QKV_LD * DD];         // w_attn^T fp16 [3072][1024]
__device__ __half g_wph[(size_t)DD * DD];             // w_proj^T fp16 [1024][1024]
__device__ __half g_ah[(size_t)MROWS * DD];           // attn out fp16
// Head-blocked fp16 for attention: [b*16+n][t][64]
__device__ __half g_qh[(size_t)NHEADS_TOT * TT * HDIM];
__device__ __half g_ql[(size_t)NHEADS_TOT * TT * HDIM];
__device__ __half g_kh[(size_t)NHEADS_TOT * TT * HDIM];
__device__ __half g_vh[(size_t)NHEADS_TOT * TT * HDIM];

// ===========================================================================
// Base-PTX helpers
// ===========================================================================
__device__ __forceinline__ uint32_t smem_u32(const void* p) {
    uint32_t a;
    asm("{ .reg .u64 t; cvta.to.shared.u64 t, %1; cvt.u32.u64 %0, t; }"
        : "=r"(a) : "l"(p));
    return a;
}

#define CP_ASYNC16(saddr, gptr) \
    asm volatile("cp.async.cg.shared.global [%0], [%1], 16;" \
                 :: "r"(saddr), "l"(gptr))
#define CP_COMMIT() asm volatile("cp.async.commit_group;" ::: "memory")
#define CP_WAIT(n)  asm volatile("cp.async.wait_group %0;" :: "n"(n) : "memory")

#define LDSM_X4(r, addr) \
    asm volatile("ldmatrix.sync.aligned.m8n8.x4.shared.b16 {%0,%1,%2,%3}, [%4];" \
                 : "=r"((r)[0]), "=r"((r)[1]), "=r"((r)[2]), "=r"((r)[3]) \
                 : "r"(addr))
#define LDSM_X4_T(r, addr) \
    asm volatile("ldmatrix.sync.aligned.m8n8.x4.trans.shared.b16 {%0,%1,%2,%3}, [%4];" \
                 : "=r"((r)[0]), "=r"((r)[1]), "=r"((r)[2]), "=r"((r)[3]) \
                 : "r"(addr))

#define MMAF16(c, a, b0, b1) \
    asm volatile("mma.sync.aligned.m16n8k16.row.col.f32.f16.f16.f32 " \
                 "{%0,%1,%2,%3},{%4,%5,%6,%7},{%8,%9},{%0,%1,%2,%3};" \
                 : "+f"((c)[0]), "+f"((c)[1]), "+f"((c)[2]), "+f"((c)[3]) \
                 : "r"((a)[0]), "r"((a)[1]), "r"((a)[2]), "r"((a)[3]), \
                   "r"(b0), "r"(b1))

// Split two fp32 into packed fp16 hi + fp16 residual (a -> low half).
__device__ __forceinline__ void split2(float a, float b,
                                       uint32_t& hi, uint32_t& lo) {
    __half ha = __float2half_rn(a), hb = __float2half_rn(b);
    __half la = __float2half_rn(a - __half2float(ha));
    __half lb = __float2half_rn(b - __half2float(hb));
    __half2 H = __halves2half2(ha, hb);
    __half2 L = __halves2half2(la, lb);
    hi = *reinterpret_cast<uint32_t*>(&H);
    lo = *reinterpret_cast<uint32_t*>(&L);
}
__device__ __forceinline__ uint32_t pkh(float a, float b) {
    __half2 H = __halves2half2(__float2half_rn(a), __float2half_rn(b));
    return *reinterpret_cast<uint32_t*>(&H);
}

// ===========================================================================
// Split fp32 -> fp16 hi/lo (elementwise), for x
// ===========================================================================
__global__ __launch_bounds__(256) void split_hilo_kernel(
    const float* __restrict__ in, __half* __restrict__ hi,
    __half* __restrict__ lo, int n4) {
    int i = blockIdx.x * 256 + threadIdx.x;
    if (i >= n4) return;
    float4 v = reinterpret_cast<const float4*>(in)[i];
    uint32_t h0, l0, h1, l1;
    split2(v.x, v.y, h0, l0);
    split2(v.z, v.w, h1, l1);
    *reinterpret_cast<uint2*>(hi + 4 * (size_t)i) = make_uint2(h0, h1);
    *reinterpret_cast<uint2*>(lo + 4 * (size_t)i) = make_uint2(l0, l1);
}

// ===========================================================================
// Transpose: w [K][N] fp32 -> out [N][K] fp16
// ===========================================================================
__global__ __launch_bounds__(256) void transpose_h_kernel(
    const float* __restrict__ w, __half* __restrict__ hi, int K, int N) {
    __shared__ float t[32][33];
    const int tx = threadIdx.x, ty = threadIdx.y;
    const int n_in = blockIdx.x * 32 + tx;
    const int k0   = blockIdx.y * 32;
#pragma unroll
    for (int j = ty; j < 32; j += 8)
        t[j][tx] = w[(size_t)(k0 + j) * N + n_in];
    __syncthreads();
    const int ko = k0 + tx;
    const int n0 = blockIdx.x * 32;
#pragma unroll
    for (int j = ty; j < 32; j += 8)
        hi[(size_t)(n0 + j) * K + ko] = __float2half_rn(t[tx][j]);
}

// ===========================================================================
// Warp-MMA fp16 GEMM: C = A @ fp16(W)^T + bias.
//   np2=1: A = Ah + Al (2 products, exact A).  np2=0: A = Ah (1 product).
// CTA 128x128, 8 warps (warp 64x32), 2-stage cp.async (96KB) -> 2 CTAs/SM.
// mode 0: fp32 C. mode 1: fused QKV epilogue (q/k/v split + head-block).
// ===========================================================================
#define GSTAGE 49152   // Ah 16K | Al 16K | Bh 16K
extern __shared__ char mm_smem[];

__global__ __launch_bounds__(256, 2) void mma_gemm8_kernel(
    const __half* __restrict__ Ahi, const __half* __restrict__ Alo,
    const __half* __restrict__ Bhi,
    const float* __restrict__ bias, float* __restrict__ C,
    float* __restrict__ v_out, int N, int K, int mode, int np2) {
    const int tid  = threadIdx.x;
    const int wid  = tid >> 5;
    const int lane = tid & 31;
    const int m0 = blockIdx.y * 128;
    const int n0 = blockIdx.x * 128;
    const uint32_t sbase = smem_u32(mm_smem);

    float acc[16][4];
#pragma unroll
    for (int i = 0; i < 16; i++)
#pragma unroll
        for (int j = 0; j < 4; j++) acc[i][j] = 0.f;

    auto issue = [&](int kc, int s) {
        const uint32_t buf = sbase + s * GSTAGE;
        const int k0 = kc * 64;
#pragma unroll
        for (int i = 0; i < 4; i++) {
            const int chunk = tid + i * 256;       // 0..1023
            const int r = chunk >> 3;              // row 0..127
            const int c = chunk & 7;               // 16B chunk 0..7
            const uint32_t soff = r * 128 + 16 * (c ^ (r & 7));
            const size_t ga = (size_t)(m0 + r) * K + k0 + c * 8;
            const size_t gb = (size_t)(n0 + r) * K + k0 + c * 8;
            CP_ASYNC16(buf + soff,         Ahi + ga);
            if (np2) CP_ASYNC16(buf + 16384 + soff, Alo + ga);
            CP_ASYNC16(buf + 32768 + soff, Bhi + gb);
        }
    };

    const int mrow0 = (wid >> 2) * 64;
    const int ncol0 = (wid & 3) * 32;
    const int a_r  = lane & 15;
    const int a_kb = lane >> 4;
    const int b_r  = ((lane >> 4) << 3) + (lane & 7);
    const int b_kb = (lane >> 3) & 1;

    auto compute = [&](int s) {
        const uint32_t buf = sbase + s * GSTAGE;
#pragma unroll
        for (int kk = 0; kk < 4; kk++) {
            uint32_t ah[4][4], al[4][4], bh[2][4];
#pragma unroll
            for (int mi = 0; mi < 4; mi++) {
                const int r  = mrow0 + mi * 16 + a_r;
                const int kb = kk * 2 + a_kb;
                const uint32_t addr = buf + r * 128 + 16 * (kb ^ (r & 7));
                LDSM_X4(ah[mi], addr);
                if (np2) LDSM_X4(al[mi], addr + 16384);
            }
#pragma unroll
            for (int nj2 = 0; nj2 < 2; nj2++) {
                const int r  = ncol0 + nj2 * 16 + b_r;
                const int kb = kk * 2 + b_kb;
                const uint32_t addr = buf + 32768 + r * 128 + 16 * (kb ^ (r & 7));
                LDSM_X4(bh[nj2], addr);
            }
            // Product-major: 16 independent MMAs between acc touches
#pragma unroll
            for (int mi = 0; mi < 4; mi++)
#pragma unroll
                for (int nj = 0; nj < 4; nj++) {
                    float* c = acc[mi * 4 + nj];
                    const int g = nj >> 1, sx = (nj & 1) * 2;
                    MMAF16(c, ah[mi], bh[g][sx], bh[g][sx + 1]);
                }
            if (np2) {
#pragma unroll
                for (int mi = 0; mi < 4; mi++)
#pragma unroll
                    for (int nj = 0; nj < 4; nj++) {
                        float* c = acc[mi * 4 + nj];
                        const int g = nj >> 1, sx = (nj & 1) * 2;
                        MMAF16(c, al[mi], bh[g][sx], bh[g][sx + 1]);
                    }
            }
        }
    };

    // ---- 2-stage double-buffered mainloop ----
    const int nch = K >> 6;
    issue(0, 0);
    CP_COMMIT();
    for (int kc = 0; kc < nch; kc++) {
        if (kc + 1 < nch) {
            issue(kc + 1, (kc + 1) & 1);
            CP_COMMIT();
            CP_WAIT(1);
        } else {
            CP_WAIT(0);
        }
        __syncthreads();
        compute(kc & 1);
        __syncthreads();
    }

    // ---- Epilogue ----
    const int rg = lane >> 2, cp2 = (lane & 3) * 2;

    auto emit_qkv = [&](int row, int col, float v0, float v1) {
        const int sector = col >> 10;           // 0=q, 1=k, 2=v
        const int cc = col & 1023;
        const int hn = cc >> 6, hd = cc & 63;
        const int b = row >> 11, t = row & 2047;
        const size_t dst = (((size_t)(b * NHEAD + hn) * TT + t) * HDIM + hd) >> 1;
        if (sector == 0) {
            v0 *= 0.125f; v1 *= 0.125f;
            uint32_t h, lo;
            split2(v0, v1, h, lo);
            reinterpret_cast<uint32_t*>(g_qh)[dst] = h;
            reinterpret_cast<uint32_t*>(g_ql)[dst] = lo;
        } else if (sector == 1) {
            reinterpret_cast<uint32_t*>(g_kh)[dst] = pkh(v0, v1);
            *reinterpret_cast<float2*>(&C[(size_t)row * DD + cc]) =
                make_float2(v0, v1);
        } else {
            reinterpret_cast<uint32_t*>(g_vh)[dst] = pkh(v0, v1);
            *reinterpret_cast<float2*>(&v_out[(size_t)row * DD + cc]) =
                make_float2(v0, v1);
        }
    };

#pragma unroll
    for (int mi = 0; mi < 4; mi++)
#pragma unroll
        for (int nj = 0; nj < 4; nj++) {
            const float* c = acc[mi * 4 + nj];
            const int row = m0 + mrow0 + mi * 16 + rg;
            const int col = n0 + ncol0 + nj * 8 + cp2;
            const float2 b2 = *reinterpret_cast<const float2*>(&bias[col]);
            const float u0 = c[0] + b2.x, u1 = c[1] + b2.y;
            const float w0 = c[2] + b2.x, w1 = c[3] + b2.y;
            if (mode == 0) {
                *reinterpret_cast<float2*>(&C[(size_t)row * N + col]) =
                    make_float2(u0, u1);
                *reinterpret_cast<float2*>(&C[(size_t)(row + 8) * N + col]) =
                    make_float2(w0, w1);
            } else {
                emit_qkv(row, col, u0, u1);
                emit_qkv(row + 8, col, w0, w1);
            }
        }
}

// ===========================================================================
// Tensor-core flash attention (fp16, causal), 128-row q-tiles.
// 256 threads, 8 warps (warp = m16). KV tiles of 64 rows.
// S = QK^T: 2 products ((qh+ql)·kh).  O += PV: 1 product (fp16(P)·Vh).
// smem: Qh|Ql (32KB) + 2 x (Kh|Vh) (2x16KB) = 64KB.
// Halves KV L2 traffic + per-tile overhead vs 64-row tiles.
// ===========================================================================
extern __shared__ char fa3_smem[];

__global__ __launch_bounds__(256) void flash7_kernel() {
    const int qt = (TT / 128 - 1) - blockIdx.x;  // reversed: heavy first
    const int hidx = blockIdx.y;                 // b*16+n
    const int tid = threadIdx.x;
    const int w = tid >> 5;                      // 0..7
    const int l = tid & 31;

    const uint32_t S = smem_u32(fa3_smem);
    const uint32_t sQh = S, sQl = S + 16384;     // each 128x64 fp16 = 16KB

    const size_t hb = (size_t)hidx * TT * HDIM;
    const __half* qh = g_qh + hb + (size_t)qt * 128 * HDIM;
    const __half* ql = g_ql + hb + (size_t)qt * 128 * HDIM;
    const __half* kh = g_kh + hb;
    const __half* vh = g_vh + hb;

    auto issueQ = [&]() {
#pragma unroll
        for (int i = 0; i < 4; i++) {
            const int chunk = tid + i * 256;     // 0..1023 (128 rows x 8)
            const int r = chunk >> 3, c = chunk & 7;
            const uint32_t soff = r * 128 + 16 * (c ^ (r & 7));
            CP_ASYNC16(sQh + soff, qh + r * HDIM + c * 8);
            CP_ASYNC16(sQl + soff, ql + r * HDIM + c * 8);
        }
    };
    auto issueKV = [&](int jt, int sel) {
        const uint32_t base = S + 32768 + sel * 16384;
        const size_t toff = (size_t)jt * 64 * HDIM;
#pragma unroll
        for (int i = 0; i < 2; i++) {
            const int chunk = tid + i * 256;     // 0..511 (64 rows x 8)
            const int r = chunk >> 3, c = chunk & 7;
            const uint32_t soff = r * 128 + 16 * (c ^ (r & 7));
            const size_t g = toff + r * HDIM + c * 8;
            CP_ASYNC16(base + soff,        kh + g);
            CP_ASYNC16(base + 8192 + soff, vh + g);
        }
    };

    issueQ();
    issueKV(0, 0);
    CP_COMMIT();

    float o[8][4];
#pragma unroll
    for (int i = 0; i < 8; i++)
#pragma unroll
        for (int j = 0; j < 4; j++) o[i][j] = 0.f;
    float m0 = -1e30f, m1 = -1e30f, l0 = 0.f, l1 = 0.f;

    const int a_r  = l & 15;
    const int a_kb = l >> 4;
    const int b_r  = ((l >> 4) << 3) + (l & 7);
    const int b_kb = (l >> 3) & 1;

    const int jmax = 2 * qt + 1;                 // last kv tile index
    for (int jt = 0; jt <= jmax; jt++) {
        if (jt < jmax) {
            issueKV(jt + 1, (jt + 1) & 1);
            CP_COMMIT();
            CP_WAIT(1);
        } else {
            CP_WAIT(0);
        }
        __syncthreads();
        const uint32_t kvb = S + 32768 + (jt & 1) * 16384;

        float s[8][4];
#pragma unroll
        for (int i = 0; i < 8; i++)
#pragma unroll
            for (int j = 0; j < 4; j++) s[i][j] = 0.f;

#pragma unroll
        for (int kk = 0; kk < 4; kk++) {
            uint32_t qh4[4], ql4[4], kh4[4][4];
            {
                const int r = w * 16 + a_r;      // 0..127
                const int kb = kk * 2 + a_kb;
                const uint32_t addr = sQh + r * 128 + 16 * (kb ^ (r & 7));
                LDSM_X4(qh4, addr);
                LDSM_X4(ql4, addr + 16384);
            }
#pragma unroll
            for (int g = 0; g < 4; g++) {
                const int r = g * 16 + b_r;
                const int kb = kk * 2 + b_kb;
                const uint32_t addr = kvb + r * 128 + 16 * (kb ^ (r & 7));
                LDSM_X4(kh4[g], addr);
            }
#pragma unroll
            for (int p = 0; p < 2; p++)
#pragma unroll
                for (int nj = 0; nj < 8; nj++) {
                    const int g = nj >> 1, sx = (nj & 1) * 2;
                    const uint32_t* aa = (p == 1) ? ql4 : qh4;
                    MMAF16(s[nj], aa, kh4[g][sx], kh4[g][sx + 1]);
                }
        }

        // ---- Causal mask (global col > row) on the last two kv tiles ----
        if (jt >= 2 * qt) {
            const int row0 = qt * 128 + w * 16 + (l >> 2);
            const int colb = jt * 64;
#pragma unroll
            for (int nj = 0; nj < 8; nj++) {
                const int col = colb + nj * 8 + 2 * (l & 3);
                if (col > row0)          s[nj][0] = -1e30f;
                if (col + 1 > row0)      s[nj][1] = -1e30f;
                if (col > row0 + 8)      s[nj][2] = -1e30f;
                if (col + 1 > row0 + 8)  s[nj][3] = -1e30f;
            }
        }

        {
            float mx0 = s[0][0], mx1 = s[0][2];
#pragma unroll
            for (int nj = 0; nj < 8; nj++) {
                mx0 = fmaxf(mx0, fmaxf(s[nj][0], s[nj][1]));
                mx1 = fmaxf(mx1, fmaxf(s[nj][2], s[nj][3]));
            }
            mx0 = fmaxf(mx0, __shfl_xor_sync(0xffffffffu, mx0, 1));
            mx0 = fmaxf(mx0, __shfl_xor_sync(0xffffffffu, mx0, 2));
            mx1 = fmaxf(mx1, __shfl_xor_sync(0xffffffffu, mx1, 1));
            mx1 = fmaxf(mx1, __shfl_xor_sync(0xffffffffu, mx1, 2));
            const float mn0 = fmaxf(m0, mx0);
            const float mn1 = fmaxf(m1, mx1);
            const float c0 = __expf(m0 - mn0);
            const float c1 = __expf(m1 - mn1);
            float rs0 = 0.f, rs1 = 0.f;
#pragma unroll
            for (int nj = 0; nj < 8; nj++) {
                s[nj][0] = __expf(s[nj][0] - mn0);
                s[nj][1] = __expf(s[nj][1] - mn0);
                s[nj][2] = __expf(s[nj][2] - mn1);
                s[nj][3] = __expf(s[nj][3] - mn1);
                rs0 += s[nj][0] + s[nj][1];
                rs1 += s[nj][2] + s[nj][3];
            }
            rs0 += __shfl_xor_sync(0xffffffffu, rs0, 1);
            rs0 += __shfl_xor_sync(0xffffffffu, rs0, 2);
            rs1 += __shfl_xor_sync(0xffffffffu, rs1, 1);
            rs1 += __shfl_xor_sync(0xffffffffu, rs1, 2);
            l0 = l0 * c0 + rs0; m0 = mn0;
            l1 = l1 * c1 + rs1; m1 = mn1;
#pragma unroll
            for (int nh = 0; nh < 8; nh++) {
                o[nh][0] *= c0; o[nh][1] *= c0;
                o[nh][2] *= c1; o[nh][3] *= c1;
            }
        }

        // ---- O += fp16(P) @ Vh (single product) ----
        const uint32_t vb = kvb + 8192;
#pragma unroll
        for (int kk = 0; kk < 4; kk++) {
            uint32_t phi[4];
            {
                const float* t0 = s[2 * kk];
                const float* t1 = s[2 * kk + 1];
                phi[0] = pkh(t0[0], t0[1]);
                phi[1] = pkh(t0[2], t0[3]);
                phi[2] = pkh(t1[0], t1[1]);
                phi[3] = pkh(t1[2], t1[3]);
            }
            uint32_t vh4[4][4];
#pragma unroll
            for (int g = 0; g < 4; g++) {
                const int row = kk * 16 + (l & 15);
                const int ch  = g * 2 + (l >> 4);
                const uint32_t addr = vb + row * 128 + 16 * (ch ^ (row & 7));
                LDSM_X4_T(vh4[g], addr);
            }
#pragma unroll
            for (int nh = 0; nh < 8; nh++) {
                const int g = nh >> 1, sx = (nh & 1) * 2;
                MMAF16(o[nh], phi, vh4[g][sx], vh4[g][sx + 1]);
            }
        }
        __syncthreads();
    }

    // ---- Epilogue: normalize, store fp16 attn-out ----
    const float inv0 = 1.0f / l0;
    const float inv1 = 1.0f / l1;
    const int b = hidx >> 4, n = hidx & 15;
    const int row0 = qt * 128 + w * 16 + (l >> 2);
#pragma unroll
    for (int nh = 0; nh < 8; nh++) {
        const int col = n * HDIM + nh * 8 + 2 * (l & 3);
        const size_t d0 = ((size_t)(b * TT + row0) * DD + col) >> 1;
        const size_t d1 = ((size_t)(b * TT + row0 + 8) * DD + col) >> 1;
        reinterpret_cast<uint32_t*>(g_ah)[d0] =
            pkh(o[nh][0] * inv0, o[nh][1] * inv0);
        reinterpret_cast<uint32_t*>(g_ah)[d1] =
            pkh(o[nh][2] * inv1, o[nh][3] * inv1);
    }
}

// ---------------------------------------------------------------------------
// Launch
// ---------------------------------------------------------------------------
extern "C" void kernel_launch(void* const* d_in, const int* in_sizes, int n_in,
                              void* d_out, int out_size) {
    (void)in_sizes; (void)n_in; (void)out_size;
    const float* x      = (const float*)d_in[0];
    const float* w_attn = (const float*)d_in[1];
    const float* b_attn = (const float*)d_in[2];
    const float* w_proj = (const float*)d_in[3];
    const float* b_proj = (const float*)d_in[4];

    float* out   = (float*)d_out;
    float* k_out = out + (size_t)MROWS * DD;
    float* v_out = k_out + (size_t)MROWS * DD;

    __half *xh, *xl, *wah, *wph, *ah;
    cudaGetSymbolAddress((void**)&xh, g_xh);
    cudaGetSymbolAddress((void**)&xl, g_xl);
    cudaGetSymbolAddress((void**)&wah, g_wah);
    cudaGetSymbolAddress((void**)&wph, g_wph);
    cudaGetSymbolAddress((void**)&ah, g_ah);

    const int MM_SMEM = 2 * GSTAGE;             // 98304 -> 2 CTAs/SM
    const int FA_SMEM = 32768 + 2 * 16384;      // 65536
    cudaFuncSetAttribute(mma_gemm8_kernel,
                         cudaFuncAttributeMaxDynamicSharedMemorySize, MM_SMEM);
    cudaFuncSetAttribute(flash7_kernel,
                         cudaFuncAttributeMaxDynamicSharedMemorySize, FA_SMEM);

    // Conversions
    split_hilo_kernel<<<(MROWS * DD / 4 + 255) / 256, 256>>>(x, xh, xl, MROWS * DD / 4);
    transpose_h_kernel<<<dim3(QKV_LD / 32, DD / 32), dim3(32, 8)>>>(
        w_attn, wah, DD, QKV_LD);
    transpose_h_kernel<<<dim3(DD / 32, DD / 32), dim3(32, 8)>>>(
        w_proj, wph, DD, DD);

    // 1) QKV projection (2-product, exact x) with fused q/k/v epilogue
    mma_gemm8_kernel<<<dim3(QKV_LD / 128, MROWS / 128), 256, MM_SMEM>>>(
        xh, xl, wah, b_attn, k_out, v_out, QKV_LD, DD, 1, 1);

    // 2) Tensor-core flash attention (128-row q-tiles)
    flash7_kernel<<<dim3(TT / 128, NHEADS_TOT), 256, FA_SMEM>>>();

    // 3) Output projection (single product — attn-out already fp16)
    mma_gemm8_kernel<<<dim3(DD / 128, MROWS / 128), 256, MM_SMEM>>>(
        ah, ah, wph, b_proj, out, nullptr, DD, DD, 0, 0);
}

// round 17
// speedup vs baseline: 1.5129x; 1.0473x over previous
#include <cuda_runtime.h>
#include <cuda_fp16.h>
#include <cstdint>
#include <cstddef>

// Problem constants
#define BB 2
#define TT 2048
#define DD 1024
#define NHEAD 16
#define HDIM 64
#define MROWS (BB * TT)        // 4096
#define QKV_LD (3 * DD)        // 3072
#define NHEADS_TOT (BB * NHEAD)

// Scratch (allocation-free rule: __device__ globals). All operands fp16.
__device__ __half g_xh[(size_t)MROWS * DD];           // x hi
__device__ __half g_xl[(size_t)MROWS * DD];           // x lo (exact split)
__device__ __half g_wah[(size_t)QKV_LD * DD];         // w_attn^T fp16 [3072][1024]
__device__ __half g_wph[(size_t)DD * DD];             // w_proj^T fp16 [1024][1024]
__device__ __half g_ah[(size_t)MROWS * DD];           // attn out fp16
// Head-blocked fp16 for attention: [b*16+n][t][64]
__device__ __half g_qh[(size_t)NHEADS_TOT * TT * HDIM];
__device__ __half g_kh[(size_t)NHEADS_TOT * TT * HDIM];
__device__ __half g_vh[(size_t)NHEADS_TOT * TT * HDIM];

// ===========================================================================
// Base-PTX helpers
// ===========================================================================
__device__ __forceinline__ uint32_t smem_u32(const void* p) {
    uint32_t a;
    asm("{ .reg .u64 t; cvta.to.shared.u64 t, %1; cvt.u32.u64 %0, t; }"
        : "=r"(a) : "l"(p));
    return a;
}

#define CP_ASYNC16(saddr, gptr) \
    asm volatile("cp.async.cg.shared.global [%0], [%1], 16;" \
                 :: "r"(saddr), "l"(gptr))
#define CP_COMMIT() asm volatile("cp.async.commit_group;" ::: "memory")
#define CP_WAIT(n)  asm volatile("cp.async.wait_group %0;" :: "n"(n) : "memory")

#define LDSM_X4(r, addr) \
    asm volatile("ldmatrix.sync.aligned.m8n8.x4.shared.b16 {%0,%1,%2,%3}, [%4];" \
                 : "=r"((r)[0]), "=r"((r)[1]), "=r"((r)[2]), "=r"((r)[3]) \
                 : "r"(addr))
#define LDSM_X4_T(r, addr) \
    asm volatile("ldmatrix.sync.aligned.m8n8.x4.trans.shared.b16 {%0,%1,%2,%3}, [%4];" \
                 : "=r"((r)[0]), "=r"((r)[1]), "=r"((r)[2]), "=r"((r)[3]) \
                 : "r"(addr))

#define MMAF16(c, a, b0, b1) \
    asm volatile("mma.sync.aligned.m16n8k16.row.col.f32.f16.f16.f32 " \
                 "{%0,%1,%2,%3},{%4,%5,%6,%7},{%8,%9},{%0,%1,%2,%3};" \
                 : "+f"((c)[0]), "+f"((c)[1]), "+f"((c)[2]), "+f"((c)[3]) \
                 : "r"((a)[0]), "r"((a)[1]), "r"((a)[2]), "r"((a)[3]), \
                   "r"(b0), "r"(b1))

// Split two fp32 into packed fp16 hi + fp16 residual (a -> low half).
__device__ __forceinline__ void split2(float a, float b,
                                       uint32_t& hi, uint32_t& lo) {
    __half ha = __float2half_rn(a), hb = __float2half_rn(b);
    __half la = __float2half_rn(a - __half2float(ha));
    __half lb = __float2half_rn(b - __half2float(hb));
    __half2 H = __halves2half2(ha, hb);
    __half2 L = __halves2half2(la, lb);
    hi = *reinterpret_cast<uint32_t*>(&H);
    lo = *reinterpret_cast<uint32_t*>(&L);
}
__device__ __forceinline__ uint32_t pkh(float a, float b) {
    __half2 H = __halves2half2(__float2half_rn(a), __float2half_rn(b));
    return *reinterpret_cast<uint32_t*>(&H);
}

// ===========================================================================
// Split fp32 -> fp16 hi/lo (elementwise), for x
// ===========================================================================
__global__ __launch_bounds__(256) void split_hilo_kernel(
    const float* __restrict__ in, __half* __restrict__ hi,
    __half* __restrict__ lo, int n4) {
    int i = blockIdx.x * 256 + threadIdx.x;
    if (i >= n4) return;
    float4 v = reinterpret_cast<const float4*>(in)[i];
    uint32_t h0, l0, h1, l1;
    split2(v.x, v.y, h0, l0);
    split2(v.z, v.w, h1, l1);
    *reinterpret_cast<uint2*>(hi + 4 * (size_t)i) = make_uint2(h0, h1);
    *reinterpret_cast<uint2*>(lo + 4 * (size_t)i) = make_uint2(l0, l1);
}

// ===========================================================================
// Transpose: w [K][N] fp32 -> out [N][K] fp16
// ===========================================================================
__global__ __launch_bounds__(256) void transpose_h_kernel(
    const float* __restrict__ w, __half* __restrict__ hi, int K, int N) {
    __shared__ float t[32][33];
    const int tx = threadIdx.x, ty = threadIdx.y;
    const int n_in = blockIdx.x * 32 + tx;
    const int k0   = blockIdx.y * 32;
#pragma unroll
    for (int j = ty; j < 32; j += 8)
        t[j][tx] = w[(size_t)(k0 + j) * N + n_in];
    __syncthreads();
    const int ko = k0 + tx;
    const int n0 = blockIdx.x * 32;
#pragma unroll
    for (int j = ty; j < 32; j += 8)
        hi[(size_t)(n0 + j) * K + ko] = __float2half_rn(t[tx][j]);
}

// ===========================================================================
// Warp-MMA fp16 GEMM: C = A @ fp16(W)^T + bias.
//   np2=1: A = Ah + Al (2 products, exact A).  np2=0: A = Ah (1 product).
// CTA 128x128, 8 warps (warp 64x32), 2-stage cp.async (96KB) -> 2 CTAs/SM.
// mode 0: fp32 C. mode 1: fused QKV epilogue (q/k/v split + head-block).
// ===========================================================================
#define GSTAGE 49152   // Ah 16K | Al 16K | Bh 16K
extern __shared__ char mm_smem[];

__global__ __launch_bounds__(256, 2) void mma_gemm8_kernel(
    const __half* __restrict__ Ahi, const __half* __restrict__ Alo,
    const __half* __restrict__ Bhi,
    const float* __restrict__ bias, float* __restrict__ C,
    float* __restrict__ v_out, int N, int K, int mode, int np2) {
    const int tid  = threadIdx.x;
    const int wid  = tid >> 5;
    const int lane = tid & 31;
    const int m0 = blockIdx.y * 128;
    const int n0 = blockIdx.x * 128;
    const uint32_t sbase = smem_u32(mm_smem);

    float acc[16][4];
#pragma unroll
    for (int i = 0; i < 16; i++)
#pragma unroll
        for (int j = 0; j < 4; j++) acc[i][j] = 0.f;

    auto issue = [&](int kc, int s) {
        const uint32_t buf = sbase + s * GSTAGE;
        const int k0 = kc * 64;
#pragma unroll
        for (int i = 0; i < 4; i++) {
            const int chunk = tid + i * 256;       // 0..1023
            const int r = chunk >> 3;              // row 0..127
            const int c = chunk & 7;               // 16B chunk 0..7
            const uint32_t soff = r * 128 + 16 * (c ^ (r & 7));
            const size_t ga = (size_t)(m0 + r) * K + k0 + c * 8;
            const size_t gb = (size_t)(n0 + r) * K + k0 + c * 8;
            CP_ASYNC16(buf + soff,         Ahi + ga);
            if (np2) CP_ASYNC16(buf + 16384 + soff, Alo + ga);
            CP_ASYNC16(buf + 32768 + soff, Bhi + gb);
        }
    };

    const int mrow0 = (wid >> 2) * 64;
    const int ncol0 = (wid & 3) * 32;
    const int a_r  = lane & 15;
    const int a_kb = lane >> 4;
    const int b_r  = ((lane >> 4) << 3) + (lane & 7);
    const int b_kb = (lane >> 3) & 1;

    auto compute = [&](int s) {
        const uint32_t buf = sbase + s * GSTAGE;
#pragma unroll
        for (int kk = 0; kk < 4; kk++) {
            uint32_t ah[4][4], al[4][4], bh[2][4];
#pragma unroll
            for (int mi = 0; mi < 4; mi++) {
                const int r  = mrow0 + mi * 16 + a_r;
                const int kb = kk * 2 + a_kb;
                const uint32_t addr = buf + r * 128 + 16 * (kb ^ (r & 7));
                LDSM_X4(ah[mi], addr);
                if (np2) LDSM_X4(al[mi], addr + 16384);
            }
#pragma unroll
            for (int nj2 = 0; nj2 < 2; nj2++) {
                const int r  = ncol0 + nj2 * 16 + b_r;
                const int kb = kk * 2 + b_kb;
                const uint32_t addr = buf + 32768 + r * 128 + 16 * (kb ^ (r & 7));
                LDSM_X4(bh[nj2], addr);
            }
            // Product-major: 16 independent MMAs between acc touches
#pragma unroll
            for (int mi = 0; mi < 4; mi++)
#pragma unroll
                for (int nj = 0; nj < 4; nj++) {
                    float* c = acc[mi * 4 + nj];
                    const int g = nj >> 1, sx = (nj & 1) * 2;
                    MMAF16(c, ah[mi], bh[g][sx], bh[g][sx + 1]);
                }
            if (np2) {
#pragma unroll
                for (int mi = 0; mi < 4; mi++)
#pragma unroll
                    for (int nj = 0; nj < 4; nj++) {
                        float* c = acc[mi * 4 + nj];
                        const int g = nj >> 1, sx = (nj & 1) * 2;
                        MMAF16(c, al[mi], bh[g][sx], bh[g][sx + 1]);
                    }
            }
        }
    };

    // ---- 2-stage double-buffered mainloop ----
    const int nch = K >> 6;
    issue(0, 0);
    CP_COMMIT();
    for (int kc = 0; kc < nch; kc++) {
        if (kc + 1 < nch) {
            issue(kc + 1, (kc + 1) & 1);
            CP_COMMIT();
            CP_WAIT(1);
        } else {
            CP_WAIT(0);
        }
        __syncthreads();
        compute(kc & 1);
        __syncthreads();
    }

    // ---- Epilogue ----
    const int rg = lane >> 2, cp2 = (lane & 3) * 2;

    auto emit_qkv = [&](int row, int col, float v0, float v1) {
        const int sector = col >> 10;           // 0=q, 1=k, 2=v
        const int cc = col & 1023;
        const int hn = cc >> 6, hd = cc & 63;
        const int b = row >> 11, t = row & 2047;
        const size_t dst = (((size_t)(b * NHEAD + hn) * TT + t) * HDIM + hd) >> 1;
        if (sector == 0) {
            reinterpret_cast<uint32_t*>(g_qh)[dst] =
                pkh(v0 * 0.125f, v1 * 0.125f);
        } else if (sector == 1) {
            reinterpret_cast<uint32_t*>(g_kh)[dst] = pkh(v0, v1);
            *reinterpret_cast<float2*>(&C[(size_t)row * DD + cc]) =
                make_float2(v0, v1);
        } else {
            reinterpret_cast<uint32_t*>(g_vh)[dst] = pkh(v0, v1);
            *reinterpret_cast<float2*>(&v_out[(size_t)row * DD + cc]) =
                make_float2(v0, v1);
        }
    };

#pragma unroll
    for (int mi = 0; mi < 4; mi++)
#pragma unroll
        for (int nj = 0; nj < 4; nj++) {
            const float* c = acc[mi * 4 + nj];
            const int row = m0 + mrow0 + mi * 16 + rg;
            const int col = n0 + ncol0 + nj * 8 + cp2;
            const float2 b2 = *reinterpret_cast<const float2*>(&bias[col]);
            const float u0 = c[0] + b2.x, u1 = c[1] + b2.y;
            const float w0 = c[2] + b2.x, w1 = c[3] + b2.y;
            if (mode == 0) {
                *reinterpret_cast<float2*>(&C[(size_t)row * N + col]) =
                    make_float2(u0, u1);
                *reinterpret_cast<float2*>(&C[(size_t)(row + 8) * N + col]) =
                    make_float2(w0, w1);
            } else {
                emit_qkv(row, col, u0, u1);
                emit_qkv(row + 8, col, w0, w1);
            }
        }
}

// ===========================================================================
// Tensor-core flash attention (fp16, causal), 128-row q-tiles.
// 256 threads, 8 warps (warp = m16). KV tiles of 64 rows.
// S = QK^T: 1 product (fp16 q · fp16 k).  O += PV: 1 product (fp16(P)·Vh).
// smem: Qh (16KB) + 2 x (Kh|Vh) (2x16KB) = 48KB.
// ===========================================================================
extern __shared__ char fa3_smem[];

__global__ __launch_bounds__(256) void flash8_kernel() {
    const int qt = (TT / 128 - 1) - blockIdx.x;  // reversed: heavy first
    const int hidx = blockIdx.y;                 // b*16+n
    const int tid = threadIdx.x;
    const int w = tid >> 5;                      // 0..7
    const int l = tid & 31;

    const uint32_t S = smem_u32(fa3_smem);
    const uint32_t sQh = S;                      // 128x64 fp16 = 16KB

    const size_t hb = (size_t)hidx * TT * HDIM;
    const __half* qh = g_qh + hb + (size_t)qt * 128 * HDIM;
    const __half* kh = g_kh + hb;
    const __half* vh = g_vh + hb;

    auto issueQ = [&]() {
#pragma unroll
        for (int i = 0; i < 4; i++) {
            const int chunk = tid + i * 256;     // 0..1023 (128 rows x 8)
            const int r = chunk >> 3, c = chunk & 7;
            const uint32_t soff = r * 128 + 16 * (c ^ (r & 7));
            CP_ASYNC16(sQh + soff, qh + r * HDIM + c * 8);
        }
    };
    auto issueKV = [&](int jt, int sel) {
        const uint32_t base = S + 16384 + sel * 16384;
        const size_t toff = (size_t)jt * 64 * HDIM;
#pragma unroll
        for (int i = 0; i < 2; i++) {
            const int chunk = tid + i * 256;     // 0..511 (64 rows x 8)
            const int r = chunk >> 3, c = chunk & 7;
            const uint32_t soff = r * 128 + 16 * (c ^ (r & 7));
            const size_t g = toff + r * HDIM + c * 8;
            CP_ASYNC16(base + soff,        kh + g);
            CP_ASYNC16(base + 8192 + soff, vh + g);
        }
    };

    issueQ();
    issueKV(0, 0);
    CP_COMMIT();

    float o[8][4];
#pragma unroll
    for (int i = 0; i < 8; i++)
#pragma unroll
        for (int j = 0; j < 4; j++) o[i][j] = 0.f;
    float m0 = -1e30f, m1 = -1e30f, l0 = 0.f, l1 = 0.f;

    const int a_r  = l & 15;
    const int a_kb = l >> 4;
    const int b_r  = ((l >> 4) << 3) + (l & 7);
    const int b_kb = (l >> 3) & 1;

    const int jmax = 2 * qt + 1;                 // last kv tile index
    for (int jt = 0; jt <= jmax; jt++) {
        if (jt < jmax) {
            issueKV(jt + 1, (jt + 1) & 1);
            CP_COMMIT();
            CP_WAIT(1);
        } else {
            CP_WAIT(0);
        }
        __syncthreads();
        const uint32_t kvb = S + 16384 + (jt & 1) * 16384;

        float s[8][4];
#pragma unroll
        for (int i = 0; i < 8; i++)
#pragma unroll
            for (int j = 0; j < 4; j++) s[i][j] = 0.f;

#pragma unroll
        for (int kk = 0; kk < 4; kk++) {
            uint32_t qh4[4], kh4[4][4];
            {
                const int r = w * 16 + a_r;      // 0..127
                const int kb = kk * 2 + a_kb;
                const uint32_t addr = sQh + r * 128 + 16 * (kb ^ (r & 7));
                LDSM_X4(qh4, addr);
            }
#pragma unroll
            for (int g = 0; g < 4; g++) {
                const int r = g * 16 + b_r;
                const int kb = kk * 2 + b_kb;
                const uint32_t addr = kvb + r * 128 + 16 * (kb ^ (r & 7));
                LDSM_X4(kh4[g], addr);
            }
#pragma unroll
            for (int nj = 0; nj < 8; nj++) {
                const int g = nj >> 1, sx = (nj & 1) * 2;
                MMAF16(s[nj], qh4, kh4[g][sx], kh4[g][sx + 1]);
            }
        }

        // ---- Causal mask (global col > row) on the last two kv tiles ----
        if (jt >= 2 * qt) {
            const int row0 = qt * 128 + w * 16 + (l >> 2);
            const int colb = jt * 64;
#pragma unroll
            for (int nj = 0; nj < 8; nj++) {
                const int col = colb + nj * 8 + 2 * (l & 3);
                if (col > row0)          s[nj][0] = -1e30f;
                if (col + 1 > row0)      s[nj][1] = -1e30f;
                if (col > row0 + 8)      s[nj][2] = -1e30f;
                if (col + 1 > row0 + 8)  s[nj][3] = -1e30f;
            }
        }

        {
            float mx0 = s[0][0], mx1 = s[0][2];
#pragma unroll
            for (int nj = 0; nj < 8; nj++) {
                mx0 = fmaxf(mx0, fmaxf(s[nj][0], s[nj][1]));
                mx1 = fmaxf(mx1, fmaxf(s[nj][2], s[nj][3]));
            }
            mx0 = fmaxf(mx0, __shfl_xor_sync(0xffffffffu, mx0, 1));
            mx0 = fmaxf(mx0, __shfl_xor_sync(0xffffffffu, mx0, 2));
            mx1 = fmaxf(mx1, __shfl_xor_sync(0xffffffffu, mx1, 1));
            mx1 = fmaxf(mx1, __shfl_xor_sync(0xffffffffu, mx1, 2));
            const float mn0 = fmaxf(m0, mx0);
            const float mn1 = fmaxf(m1, mx1);
            const float c0 = __expf(m0 - mn0);
            const float c1 = __expf(m1 - mn1);
            float rs0 = 0.f, rs1 = 0.f;
#pragma unroll
            for (int nj = 0; nj < 8; nj++) {
                s[nj][0] = __expf(s[nj][0] - mn0);
                s[nj][1] = __expf(s[nj][1] - mn0);
                s[nj][2] = __expf(s[nj][2] - mn1);
                s[nj][3] = __expf(s[nj][3] - mn1);
                rs0 += s[nj][0] + s[nj][1];
                rs1 += s[nj][2] + s[nj][3];
            }
            rs0 += __shfl_xor_sync(0xffffffffu, rs0, 1);
            rs0 += __shfl_xor_sync(0xffffffffu, rs0, 2);
            rs1 += __shfl_xor_sync(0xffffffffu, rs1, 1);
            rs1 += __shfl_xor_sync(0xffffffffu, rs1, 2);
            l0 = l0 * c0 + rs0; m0 = mn0;
            l1 = l1 * c1 + rs1; m1 = mn1;
#pragma unroll
            for (int nh = 0; nh < 8; nh++) {
                o[nh][0] *= c0; o[nh][1] *= c0;
                o[nh][2] *= c1; o[nh][3] *= c1;
            }
        }

        // ---- O += fp16(P) @ Vh (single product) ----
        const uint32_t vb = kvb + 8192;
#pragma unroll
        for (int kk = 0; kk < 4; kk++) {
            uint32_t phi[4];
            {
                const float* t0 = s[2 * kk];
                const float* t1 = s[2 * kk + 1];
                phi[0] = pkh(t0[0], t0[1]);
                phi[1] = pkh(t0[2], t0[3]);
                phi[2] = pkh(t1[0], t1[1]);
                phi[3] = pkh(t1[2], t1[3]);
            }
            uint32_t vh4[4][4];
#pragma unroll
            for (int g = 0; g < 4; g++) {
                const int row = kk * 16 + (l & 15);
                const int ch  = g * 2 + (l >> 4);
                const uint32_t addr = vb + row * 128 + 16 * (ch ^ (row & 7));
                LDSM_X4_T(vh4[g], addr);
            }
#pragma unroll
            for (int nh = 0; nh < 8; nh++) {
                const int g = nh >> 1, sx = (nh & 1) * 2;
                MMAF16(o[nh], phi, vh4[g][sx], vh4[g][sx + 1]);
            }
        }
        __syncthreads();
    }

    // ---- Epilogue: normalize, store fp16 attn-out ----
    const float inv0 = 1.0f / l0;
    const float inv1 = 1.0f / l1;
    const int b = hidx >> 4, n = hidx & 15;
    const int row0 = qt * 128 + w * 16 + (l >> 2);
#pragma unroll
    for (int nh = 0; nh < 8; nh++) {
        const int col = n * HDIM + nh * 8 + 2 * (l & 3);
        const size_t d0 = ((size_t)(b * TT + row0) * DD + col) >> 1;
        const size_t d1 = ((size_t)(b * TT + row0 + 8) * DD + col) >> 1;
        reinterpret_cast<uint32_t*>(g_ah)[d0] =
            pkh(o[nh][0] * inv0, o[nh][1] * inv0);
        reinterpret_cast<uint32_t*>(g_ah)[d1] =
            pkh(o[nh][2] * inv1, o[nh][3] * inv1);
    }
}

// ---------------------------------------------------------------------------
// Launch
// ---------------------------------------------------------------------------
extern "C" void kernel_launch(void* const* d_in, const int* in_sizes, int n_in,
                              void* d_out, int out_size) {
    (void)in_sizes; (void)n_in; (void)out_size;
    const float* x      = (const float*)d_in[0];
    const float* w_attn = (const float*)d_in[1];
    const float* b_attn = (const float*)d_in[2];
    const float* w_proj = (const float*)d_in[3];
    const float* b_proj = (const float*)d_in[4];

    float* out   = (float*)d_out;
    float* k_out = out + (size_t)MROWS * DD;
    float* v_out = k_out + (size_t)MROWS * DD;

    __half *xh, *xl, *wah, *wph, *ah;
    cudaGetSymbolAddress((void**)&xh, g_xh);
    cudaGetSymbolAddress((void**)&xl, g_xl);
    cudaGetSymbolAddress((void**)&wah, g_wah);
    cudaGetSymbolAddress((void**)&wph, g_wph);
    cudaGetSymbolAddress((void**)&ah, g_ah);

    const int MM_SMEM = 2 * GSTAGE;             // 98304 -> 2 CTAs/SM
    const int FA_SMEM = 16384 + 2 * 16384;      // 49152
    cudaFuncSetAttribute(mma_gemm8_kernel,
                         cudaFuncAttributeMaxDynamicSharedMemorySize, MM_SMEM);
    cudaFuncSetAttribute(flash8_kernel,
                         cudaFuncAttributeMaxDynamicSharedMemorySize, FA_SMEM);

    // Conversions
    split_hilo_kernel<<<(MROWS * DD / 4 + 255) / 256, 256>>>(x, xh, xl, MROWS * DD / 4);
    transpose_h_kernel<<<dim3(QKV_LD / 32, DD / 32), dim3(32, 8)>>>(
        w_attn, wah, DD, QKV_LD);
    transpose_h_kernel<<<dim3(DD / 32, DD / 32), dim3(32, 8)>>>(
        w_proj, wph, DD, DD);

    // 1) QKV projection (2-product, exact x) with fused q/k/v epilogue
    mma_gemm8_kernel<<<dim3(QKV_LD / 128, MROWS / 128), 256, MM_SMEM>>>(
        xh, xl, wah, b_attn, k_out, v_out, QKV_LD, DD, 1, 1);

    // 2) Tensor-core flash attention (S 1-product, PV 1-product, 128-row tiles)
    flash8_kernel<<<dim3(TT / 128, NHEADS_TOT), 256, FA_SMEM>>>();

    // 3) Output projection (single product — attn-out already fp16)
    mma_gemm8_kernel<<<dim3(DD / 128, MROWS / 128), 256, MM_SMEM>>>(
        ah, ah, wph, b_proj, out, nullptr, DD, DD, 0, 0);
}